// round 12
// baseline (speedup 1.0000x reference)
#include <cuda_runtime.h>
#include <math.h>

// Problem constants
#define NPTS   30000
#define CDIM   128
#define SDIM   16      // neighbors
#define HDIM   8       // heads
#define DDIM   16      // dims per head
#define OSDIM  16      // O / SHARE
#define EPSLN  1e-5f

#define MTILES 235                 // ceil(30000/128)
#define GEMM_BLOCKS (MTILES * 3)
#define PE_BLOCKS   ((NPTS * SDIM + 255) / 256)

// dynamic smem for GEMM: sx = 2*128*16 floats, sw = 2*16*132 float2
#define SX_FLOATS (2 * 128 * 16)
#define SW_F2     (2 * 16 * 132)
#define SMEM_BYTES (SX_FLOATS * 4 + SW_F2 * 8)

// Scratch (no cudaMalloc allowed)
__device__ float  g_q[NPTS * CDIM];
__device__ float  g_k[NPTS * CDIM];
__device__ float  g_v[NPTS * CDIM];
__device__ float4 g_a3[NPTS * SDIM];        // relu(ln(pr@Wp1+bp1)) per (n,s)
__device__ float2 g_ws[3 * CDIM * CDIM];    // pre-split (hi,lo) of Wq,Wk,Wv

// ---------------------------------------------------------------------------
// tf32 helpers
// ---------------------------------------------------------------------------
__device__ __forceinline__ unsigned tf32_rna(float v) {
    unsigned r;
    asm("cvt.rna.tf32.f32 %0, %1;" : "=r"(r) : "f"(v));
    return r;
}
__device__ __forceinline__ float2 tf32_split(float v) {
    const unsigned hb = tf32_rna(v);
    const float hf = __uint_as_float(hb);
    const unsigned lb = tf32_rna(v - hf);
    return make_float2(hf, __uint_as_float(lb));
}

__device__ __forceinline__ void mma_tf32(float* d, const unsigned* a,
                                         unsigned b0, unsigned b1) {
    asm volatile(
        "mma.sync.aligned.m16n8k8.row.col.f32.tf32.tf32.f32 "
        "{%0,%1,%2,%3}, {%4,%5,%6,%7}, {%8,%9}, {%0,%1,%2,%3};"
        : "+f"(d[0]), "+f"(d[1]), "+f"(d[2]), "+f"(d[3])
        : "r"(a[0]), "r"(a[1]), "r"(a[2]), "r"(a[3]), "r"(b0), "r"(b1));
}

__device__ __forceinline__ void cp_async16(void* smem_dst, const void* gmem_src) {
    unsigned s = (unsigned)__cvta_generic_to_shared(smem_dst);
    asm volatile("cp.async.ca.shared.global [%0], [%1], 16;\n"
                 :: "r"(s), "l"(gmem_src));
}

// ---------------------------------------------------------------------------
// W split precompute (small: 3*128*128 elements)
// ---------------------------------------------------------------------------
__global__ __launch_bounds__(256) void w_split(
    const float* __restrict__ Wq, const float* __restrict__ Wk,
    const float* __restrict__ Wv)
{
    const int i = blockIdx.x * 256 + threadIdx.x;
    if (i >= 3 * CDIM * CDIM) return;
    const int mat = i / (CDIM * CDIM);
    const int e   = i - mat * CDIM * CDIM;
    const float v = (mat == 0) ? Wq[e] : (mat == 1) ? Wk[e] : Wv[e];
    g_ws[i] = tf32_split(v);
}

// ---------------------------------------------------------------------------
// Combined mid kernel (unchanged from R11):
//   blocks [0, GEMM_BLOCKS)          : tf32 QKV GEMM tiles (x tf32, W hi/lo)
//   blocks [GEMM_BLOCKS, +PE_BLOCKS) : positional precompute (a3)
// ---------------------------------------------------------------------------
__global__ __launch_bounds__(256, 2) void mid_fused(
    const float* __restrict__ x,
    const float* __restrict__ bq, const float* __restrict__ bk,
    const float* __restrict__ bv,
    const float* __restrict__ p,  const int* __restrict__ idx,
    const float* __restrict__ Wp1, const float* __restrict__ bp1,
    const float* __restrict__ gp,  const float* __restrict__ betap)
{
    const int bid = blockIdx.x;
    const int tid = threadIdx.x;

    if (bid >= GEMM_BLOCKS) {
        const int t = (bid - GEMM_BLOCKS) * 256 + tid;
        if (t >= NPTS * SDIM) return;
        const int n = t >> 4;
        const int j = idx[t];

        const float pr0 = p[j * 3 + 0] - p[n * 3 + 0];
        const float pr1 = p[j * 3 + 1] - p[n * 3 + 1];
        const float pr2 = p[j * 3 + 2] - p[n * 3 + 2];

        float t0 = fmaf(pr2, Wp1[6], fmaf(pr1, Wp1[3], fmaf(pr0, Wp1[0], bp1[0])));
        float t1 = fmaf(pr2, Wp1[7], fmaf(pr1, Wp1[4], fmaf(pr0, Wp1[1], bp1[1])));
        float t2 = fmaf(pr2, Wp1[8], fmaf(pr1, Wp1[5], fmaf(pr0, Wp1[2], bp1[2])));
        const float mp  = (t0 + t1 + t2) * (1.f / 3.f);
        const float e0 = t0 - mp, e1 = t1 - mp, e2 = t2 - mp;
        const float vp  = (e0 * e0 + e1 * e1 + e2 * e2) * (1.f / 3.f);
        const float ivp = rsqrtf(vp + EPSLN);
        const float a0 = fmaxf(fmaf(e0 * ivp, gp[0], betap[0]), 0.f);
        const float a1 = fmaxf(fmaf(e1 * ivp, gp[1], betap[1]), 0.f);
        const float a2 = fmaxf(fmaf(e2 * ivp, gp[2], betap[2]), 0.f);
        g_a3[t] = make_float4(a0, a1, a2, 0.f);
        return;
    }

    extern __shared__ float smf[];
    float*  sx = smf;                          // [2][128][16] (tf32 x)
    float2* sw = (float2*)(smf + SX_FLOATS);   // [2][16][132] (hi,lo W)

    const int mat   = bid % 3;
    const int mtile = bid / 3;
    const int row0  = mtile * 128;

    const float* __restrict__ bias = (mat == 0) ? bq : (mat == 1) ? bk : bv;
    float* __restrict__ out        = (mat == 0) ? g_q : (mat == 1) ? g_k : g_v;
    const float2* __restrict__ Ws  = g_ws + (size_t)mat * CDIM * CDIM;

    const int lane   = tid & 31;
    const int wid    = tid >> 5;
    const int warp_m = wid & 3;
    const int warp_n = wid >> 2;
    const int lg  = lane >> 2;
    const int lt  = lane & 3;

    const int xrow = tid >> 1;
    const int xko  = (tid & 1) * 8;
    const bool xvalid = (row0 + xrow) < NPTS;
    const float* xbase = x + (size_t)(row0 + xrow) * CDIM + xko;

    float d[2][8][4];
#pragma unroll
    for (int g = 0; g < 2; g++)
#pragma unroll
        for (int nb = 0; nb < 8; nb++)
#pragma unroll
            for (int c = 0; c < 4; c++) d[g][nb][c] = 0.f;

    auto stage_w = [&](int st, int k0) {
#pragma unroll
        for (int i = 0; i < 4; i++) {
            const int li  = tid * 4 + i;
            const int wk  = li >> 6;
            const int wn2 = (li & 63) * 2;
            cp_async16(&sw[(st * 16 + wk) * 132 + wn2],
                       Ws + (size_t)(k0 + wk) * CDIM + wn2);
        }
        asm volatile("cp.async.commit_group;");
    };
    auto cvt4 = [&](float4 v) {
        return make_float4(__uint_as_float(tf32_rna(v.x)),
                           __uint_as_float(tf32_rna(v.y)),
                           __uint_as_float(tf32_rna(v.z)),
                           __uint_as_float(tf32_rna(v.w)));
    };
    auto store_x = [&](int st, float4 xa, float4 xb) {
        *(float4*)&sx[(st * 128 + xrow) * 16 + xko    ] = cvt4(xa);
        *(float4*)&sx[(st * 128 + xrow) * 16 + xko + 4] = cvt4(xb);
    };

    stage_w(0, 0);
    {
        float4 xa = make_float4(0.f, 0.f, 0.f, 0.f), xb = xa;
        if (xvalid) { xa = *(const float4*)(xbase); xb = *(const float4*)(xbase + 4); }
        store_x(0, xa, xb);
    }
    asm volatile("cp.async.wait_group 0;");
    __syncthreads();

#pragma unroll 1
    for (int c = 0; c < 8; c++) {
        const int cur = c & 1;
        const bool more = (c < 7);

        float4 xa, xb;
        if (more) {
            stage_w(cur ^ 1, (c + 1) * 16);
            xa = make_float4(0.f, 0.f, 0.f, 0.f); xb = xa;
            if (xvalid) {
                xa = *(const float4*)(xbase + (c + 1) * 16);
                xb = *(const float4*)(xbase + (c + 1) * 16 + 4);
            }
        }

#pragma unroll
        for (int ks = 0; ks < 2; ks++) {
            const int kb = ks * 8;
            unsigned a_hi[2][4];
#pragma unroll
            for (int g = 0; g < 2; g++) {
                const int rb = warp_m * 32 + g * 16;
                a_hi[g][0] = __float_as_uint(sx[(cur * 128 + rb + lg    ) * 16 + kb + lt    ]);
                a_hi[g][1] = __float_as_uint(sx[(cur * 128 + rb + lg + 8) * 16 + kb + lt    ]);
                a_hi[g][2] = __float_as_uint(sx[(cur * 128 + rb + lg    ) * 16 + kb + lt + 4]);
                a_hi[g][3] = __float_as_uint(sx[(cur * 128 + rb + lg + 8) * 16 + kb + lt + 4]);
            }
#pragma unroll
            for (int nb = 0; nb < 8; nb++) {
                const int ncol = warp_n * 64 + nb * 8 + lg;
                const float2 b0v = sw[(cur * 16 + kb + lt    ) * 132 + ncol];
                const float2 b1v = sw[(cur * 16 + kb + lt + 4) * 132 + ncol];
                const unsigned bh0 = __float_as_uint(b0v.x), bl0 = __float_as_uint(b0v.y);
                const unsigned bh1 = __float_as_uint(b1v.x), bl1 = __float_as_uint(b1v.y);
#pragma unroll
                for (int g = 0; g < 2; g++) {
                    mma_tf32(d[g][nb], a_hi[g], bh0, bh1);   // x * W_hi
                    mma_tf32(d[g][nb], a_hi[g], bl0, bl1);   // x * W_lo
                }
            }
        }

        if (more) {
            store_x(cur ^ 1, xa, xb);
            asm volatile("cp.async.wait_group 0;");
        }
        __syncthreads();
    }

#pragma unroll
    for (int nb = 0; nb < 8; nb++) {
        const int col = warp_n * 64 + nb * 8 + lt * 2;
        const float2 bs = *(const float2*)(bias + col);
#pragma unroll
        for (int g = 0; g < 2; g++) {
            const int rbase = row0 + warp_m * 32 + g * 16 + lg;
            if (rbase < NPTS) {
                float2 o = make_float2(d[g][nb][0] + bs.x, d[g][nb][1] + bs.y);
                *(float2*)(out + (size_t)rbase * CDIM + col) = o;
            }
            if (rbase + 8 < NPTS) {
                float2 o = make_float2(d[g][nb][2] + bs.x, d[g][nb][3] + bs.y);
                *(float2*)(out + (size_t)(rbase + 8) * CDIM + col) = o;
            }
        }
    }
}

// ---------------------------------------------------------------------------
// Fused point-transformer kernel — SINGLE PASS with max-free online softmax.
// Logits are bounded (LN2-normalized activations dotted with rowmean(Ww2)),
// so exp() without max subtraction is numerically safe; softmax is
// shift-invariant so the constant mean(bw2) is dropped entirely.
// Per token: e = exp(l); se += e; acc += e*v; A += e*a3.  Pass 2 eliminated.
// ---------------------------------------------------------------------------
__global__ __launch_bounds__(256, 3) void pt_fused(
    const int*   __restrict__ idx,
    const float* __restrict__ Wp2, const float* __restrict__ bp2,
    const float* __restrict__ gw1, const float* __restrict__ betaw1,
    const float* __restrict__ Ww1, const float* __restrict__ bw1,
    const float* __restrict__ gw2, const float* __restrict__ betaw2,
    const float* __restrict__ Ww2, const float* __restrict__ bw2,
    float* __restrict__ out)
{
    __shared__ float sWw1[16][16];
    __shared__ float sWw2[16][16];
    __shared__ int   sidx[8][SDIM];
    __shared__ float sa[8][4][HDIM][16];

    const int tid  = threadIdx.x;
    const int pt   = tid >> 5;
    const int lane = tid & 31;
    const int n    = blockIdx.x * 8 + pt;
    const int ch4  = lane * 4;
    const int qq   = lane & 3;
    const int d4   = qq * 4;
    const int hh   = lane >> 2;
    const unsigned FULL = 0xffffffffu;

    {
        float* w1f = &sWw1[0][0];
        float* w2f = &sWw2[0][0];
        w1f[tid] = Ww1[tid];
        w2f[tid] = Ww2[tid];
    }
    if (lane < SDIM) sidx[pt][lane] = idx[n * SDIM + lane];
    __syncthreads();

    const float4 xq4   = *(const float4*)(g_q + (size_t)n * CDIM + ch4);
    const float4 wp2c0 = *(const float4*)(Wp2 + 0 * CDIM + ch4);
    const float4 wp2c1 = *(const float4*)(Wp2 + 1 * CDIM + ch4);
    const float4 wp2c2 = *(const float4*)(Wp2 + 2 * CDIM + ch4);
    const float4 bp24  = *(const float4*)(bp2 + ch4);
    const float4 g14   = *(const float4*)(gw1    + d4);
    const float4 be14  = *(const float4*)(betaw1 + d4);
    const float4 b14   = *(const float4*)(bw1    + d4);
    const float4 g24   = *(const float4*)(gw2    + d4);
    const float4 be24  = *(const float4*)(betaw2 + d4);

    // fold matvec2: cm[d] = rowmean_o(Ww2[d][:]) for this lane's 4 d's
    float4 cm;
    {
        float s0 = 0.f, s1 = 0.f, s2 = 0.f, s3 = 0.f;
#pragma unroll
        for (int j = 0; j < 4; j++) {
            const float4 v0 = *(const float4*)&sWw2[d4 + 0][j * 4];
            const float4 v1 = *(const float4*)&sWw2[d4 + 1][j * 4];
            const float4 v2 = *(const float4*)&sWw2[d4 + 2][j * 4];
            const float4 v3 = *(const float4*)&sWw2[d4 + 3][j * 4];
            s0 += v0.x + v0.y + v0.z + v0.w;
            s1 += v1.x + v1.y + v1.z + v1.w;
            s2 += v2.x + v2.y + v2.z + v2.w;
            s3 += v3.x + v3.y + v3.z + v3.w;
        }
        cm = make_float4(s0 * (1.f / 16.f), s1 * (1.f / 16.f),
                         s2 * (1.f / 16.f), s3 * (1.f / 16.f));
    }

    const int sslot = ((qq + hh) & 3) * 4;

    // online accumulators (per point / per head channels)
    float4 acc = make_float4(0.f, 0.f, 0.f, 0.f);
    float A0 = 0.f, A1 = 0.f, A2 = 0.f;
    float se = 0.f;

#pragma unroll 1
    for (int s = 0; s < SDIM; s += 4) {
        float4 r[4], a3[4];
#pragma unroll
        for (int u = 0; u < 4; u++) {
            const int j = sidx[pt][s + u];
            r[u]  = *(const float4*)(g_k + (size_t)j * CDIM + ch4);
            a3[u] = g_a3[n * SDIM + s + u];
        }

        // r = kg + pe - xq ; single-pass LN1 sums
        float sm[4], sq[4];
#pragma unroll
        for (int u = 0; u < 4; u++) {
            r[u].x += fmaf(a3[u].x, wp2c0.x, fmaf(a3[u].y, wp2c1.x, fmaf(a3[u].z, wp2c2.x, bp24.x))) - xq4.x;
            r[u].y += fmaf(a3[u].x, wp2c0.y, fmaf(a3[u].y, wp2c1.y, fmaf(a3[u].z, wp2c2.y, bp24.y))) - xq4.y;
            r[u].z += fmaf(a3[u].x, wp2c0.z, fmaf(a3[u].y, wp2c1.z, fmaf(a3[u].z, wp2c2.z, bp24.z))) - xq4.z;
            r[u].w += fmaf(a3[u].x, wp2c0.w, fmaf(a3[u].y, wp2c1.w, fmaf(a3[u].z, wp2c2.w, bp24.w))) - xq4.w;
            sm[u] = r[u].x + r[u].y + r[u].z + r[u].w;
            sq[u] = r[u].x * r[u].x + r[u].y * r[u].y + r[u].z * r[u].z + r[u].w * r[u].w;
        }
#pragma unroll
        for (int u = 0; u < 4; u++) { sm[u] += __shfl_xor_sync(FULL, sm[u], 1, 4);
                                      sq[u] += __shfl_xor_sync(FULL, sq[u], 1, 4); }
#pragma unroll
        for (int u = 0; u < 4; u++) { sm[u] += __shfl_xor_sync(FULL, sm[u], 2, 4);
                                      sq[u] += __shfl_xor_sync(FULL, sq[u], 2, 4); }
#pragma unroll
        for (int u = 0; u < 4; u++) {
            const float mean = sm[u] * (1.f / 16.f);
            const float var  = fmaf(-mean, mean, sq[u] * (1.f / 16.f));
            const float inv  = rsqrtf(var + EPSLN);
            float4 a;
            a.x = fmaxf(fmaf((r[u].x - mean) * inv, g14.x, be14.x), 0.f);
            a.y = fmaxf(fmaf((r[u].y - mean) * inv, g14.y, be14.y), 0.f);
            a.z = fmaxf(fmaf((r[u].z - mean) * inv, g14.z, be14.z), 0.f);
            a.w = fmaxf(fmaf((r[u].w - mean) * inv, g14.w, be14.w), 0.f);
            *(float4*)&sa[pt][u][hh][sslot] = a;
        }
        __syncwarp();

        // prefetch v rows for this token group (consumed after logits)
        float4 vv[4];
#pragma unroll
        for (int u = 0; u < 4; u++)
            vv[u] = *(const float4*)(g_v + (size_t)sidx[pt][s + u] * CDIM + ch4);

        // matvec1: weights shared across all 4 tokens
        float4 w[4];
#pragma unroll
        for (int u = 0; u < 4; u++) w[u] = b14;
#pragma unroll
        for (int q = 0; q < 4; q++) {
            const float4 c0 = *(const float4*)&sWw1[q * 4 + 0][d4];
            const float4 c1 = *(const float4*)&sWw1[q * 4 + 1][d4];
            const float4 c2 = *(const float4*)&sWw1[q * 4 + 2][d4];
            const float4 c3 = *(const float4*)&sWw1[q * 4 + 3][d4];
            const int ps = ((q + hh) & 3) * 4;
#pragma unroll
            for (int u = 0; u < 4; u++) {
                const float4 a = *(const float4*)&sa[pt][u][hh][ps];
                w[u].x = fmaf(a.x, c0.x, fmaf(a.y, c1.x, fmaf(a.z, c2.x, fmaf(a.w, c3.x, w[u].x))));
                w[u].y = fmaf(a.x, c0.y, fmaf(a.y, c1.y, fmaf(a.z, c2.y, fmaf(a.w, c3.y, w[u].y))));
                w[u].z = fmaf(a.x, c0.z, fmaf(a.y, c1.z, fmaf(a.z, c2.z, fmaf(a.w, c3.z, w[u].z))));
                w[u].w = fmaf(a.x, c0.w, fmaf(a.y, c1.w, fmaf(a.z, c2.w, fmaf(a.w, c3.w, w[u].w))));
            }
        }
        __syncwarp();

        // LN2 sums (single-pass, batched shuffles)
#pragma unroll
        for (int u = 0; u < 4; u++) {
            sm[u] = w[u].x + w[u].y + w[u].z + w[u].w;
            sq[u] = w[u].x * w[u].x + w[u].y * w[u].y + w[u].z * w[u].z + w[u].w * w[u].w;
        }
#pragma unroll
        for (int u = 0; u < 4; u++) { sm[u] += __shfl_xor_sync(FULL, sm[u], 1, 4);
                                      sq[u] += __shfl_xor_sync(FULL, sq[u], 1, 4); }
#pragma unroll
        for (int u = 0; u < 4; u++) { sm[u] += __shfl_xor_sync(FULL, sm[u], 2, 4);
                                      sq[u] += __shfl_xor_sync(FULL, sq[u], 2, 4); }

        float l[4];
#pragma unroll
        for (int u = 0; u < 4; u++) {
            const float mean = sm[u] * (1.f / 16.f);
            const float var  = fmaf(-mean, mean, sq[u] * (1.f / 16.f));
            const float inv  = rsqrtf(var + EPSLN);
            const float ex = fmaxf(fmaf((w[u].x - mean) * inv, g24.x, be24.x), 0.f);
            const float ey = fmaxf(fmaf((w[u].y - mean) * inv, g24.y, be24.y), 0.f);
            const float ez = fmaxf(fmaf((w[u].z - mean) * inv, g24.z, be24.z), 0.f);
            const float ew = fmaxf(fmaf((w[u].w - mean) * inv, g24.w, be24.w), 0.f);
            l[u] = fmaf(ex, cm.x, fmaf(ey, cm.y, fmaf(ez, cm.z, ew * cm.w)));
        }
#pragma unroll
        for (int u = 0; u < 4; u++) l[u] += __shfl_xor_sync(FULL, l[u], 1, 4);
#pragma unroll
        for (int u = 0; u < 4; u++) l[u] += __shfl_xor_sync(FULL, l[u], 2, 4);

        // online accumulation (max-free: logits bounded by LN2 normalization)
#pragma unroll
        for (int u = 0; u < 4; u++) {
            const float e = __expf(l[u]);
            se += e;
            acc.x = fmaf(vv[u].x, e, acc.x);
            acc.y = fmaf(vv[u].y, e, acc.y);
            acc.z = fmaf(vv[u].z, e, acc.z);
            acc.w = fmaf(vv[u].w, e, acc.w);
            A0 = fmaf(a3[u].x, e, A0);
            A1 = fmaf(a3[u].y, e, A1);
            A2 = fmaf(a3[u].z, e, A2);
        }
    }

    // normalize + pe fold (sum_s w_s = 1 => pe part = (A/se)@Wp2 + bp2)
    const float rse = 1.f / se;
    acc.x *= rse; acc.y *= rse; acc.z *= rse; acc.w *= rse;
    A0 *= rse; A1 *= rse; A2 *= rse;

    float4 o;
    o.x = acc.x + fmaf(A0, wp2c0.x, fmaf(A1, wp2c1.x, fmaf(A2, wp2c2.x, bp24.x)));
    o.y = acc.y + fmaf(A0, wp2c0.y, fmaf(A1, wp2c1.y, fmaf(A2, wp2c2.y, bp24.y)));
    o.z = acc.z + fmaf(A0, wp2c0.z, fmaf(A1, wp2c1.z, fmaf(A2, wp2c2.z, bp24.z)));
    o.w = acc.w + fmaf(A0, wp2c0.w, fmaf(A1, wp2c1.w, fmaf(A2, wp2c2.w, bp24.w)));
    *(float4*)(out + (size_t)n * CDIM + ch4) = o;
}

// ---------------------------------------------------------------------------
extern "C" void kernel_launch(void* const* d_in, const int* in_sizes, int n_in,
                              void* d_out, int out_size)
{
    const float* p      = (const float*)d_in[0];
    const float* x      = (const float*)d_in[1];
    const int*   idx    = (const int*)  d_in[2];
    const float* Wq     = (const float*)d_in[3];
    const float* bq     = (const float*)d_in[4];
    const float* Wk     = (const float*)d_in[5];
    const float* bk     = (const float*)d_in[6];
    const float* Wv     = (const float*)d_in[7];
    const float* bv     = (const float*)d_in[8];
    const float* Wp1    = (const float*)d_in[9];
    const float* bp1    = (const float*)d_in[10];
    const float* gp     = (const float*)d_in[11];
    const float* betap  = (const float*)d_in[12];
    const float* Wp2    = (const float*)d_in[13];
    const float* bp2    = (const float*)d_in[14];
    const float* gw1    = (const float*)d_in[15];
    const float* betaw1 = (const float*)d_in[16];
    const float* Ww1    = (const float*)d_in[17];
    const float* bw1    = (const float*)d_in[18];
    const float* gw2    = (const float*)d_in[19];
    const float* betaw2 = (const float*)d_in[20];
    const float* Ww2    = (const float*)d_in[21];
    const float* bw2    = (const float*)d_in[22];
    float* out = (float*)d_out;

    cudaFuncSetAttribute(mid_fused, cudaFuncAttributeMaxDynamicSharedMemorySize,
                         SMEM_BYTES);

    w_split<<<(3 * CDIM * CDIM + 255) / 256, 256>>>(Wq, Wk, Wv);

    mid_fused<<<GEMM_BLOCKS + PE_BLOCKS, 256, SMEM_BYTES>>>(
        x, bq, bk, bv, p, idx, Wp1, bp1, gp, betap);

    pt_fused<<<NPTS / 8, 256>>>(idx,
                                Wp2, bp2,
                                gw1, betaw1, Ww1, bw1,
                                gw2, betaw2, Ww2, bw2, out);
}

// round 13
// speedup vs baseline: 1.0565x; 1.0565x over previous
#include <cuda_runtime.h>
#include <cuda_bf16.h>
#include <math.h>

// Problem constants
#define NPTS   30000
#define CDIM   128
#define SDIM   16      // neighbors
#define HDIM   8       // heads
#define DDIM   16      // dims per head
#define OSDIM  16      // O / SHARE
#define EPSLN  1e-5f

#define MTILES 235                 // ceil(30000/128)
#define GEMM_BLOCKS (MTILES * 3)
#define PE_BLOCKS   ((NPTS * SDIM + 255) / 256)

// dynamic smem (uint2 units): sx = 2 stages x 128 rows x 8 kp, sw same
#define SX_U2 (2 * 128 * 8)
#define SW_U2 (2 * 128 * 8)
#define SMEM_BYTES ((SX_U2 + SW_U2) * 8)

// Scratch (no cudaMalloc allowed)
__device__ float  g_q[NPTS * CDIM];
__device__ float  g_k[NPTS * CDIM];
__device__ float  g_v[NPTS * CDIM];
__device__ float4 g_a3[NPTS * SDIM];     // relu(ln(pr@Wp1+bp1)) per (n,s)
__device__ uint2  g_wt[3 * CDIM * 64];   // W transposed: [mat][n][kp] -> (hi bf16x2, lo bf16x2)

// ---------------------------------------------------------------------------
// bf16 split helpers
// ---------------------------------------------------------------------------
__device__ __forceinline__ uint2 splitpack_bf16(float a, float b) {
    const __nv_bfloat16 ha = __float2bfloat16(a);
    const __nv_bfloat16 hb = __float2bfloat16(b);
    const float ra = a - __bfloat162float(ha);
    const float rb = b - __bfloat162float(hb);
    uint2 o;
    o.x = (unsigned)__bfloat16_as_ushort(ha) |
          ((unsigned)__bfloat16_as_ushort(hb) << 16);
    o.y = (unsigned)__bfloat16_as_ushort(__float2bfloat16(ra)) |
          ((unsigned)__bfloat16_as_ushort(__float2bfloat16(rb)) << 16);
    return o;
}

__device__ __forceinline__ void mma_bf16(float* d, const unsigned* a,
                                         unsigned b0, unsigned b1) {
    asm volatile(
        "mma.sync.aligned.m16n8k16.row.col.f32.bf16.bf16.f32 "
        "{%0,%1,%2,%3}, {%4,%5,%6,%7}, {%8,%9}, {%0,%1,%2,%3};"
        : "+f"(d[0]), "+f"(d[1]), "+f"(d[2]), "+f"(d[3])
        : "r"(a[0]), "r"(a[1]), "r"(a[2]), "r"(a[3]), "r"(b0), "r"(b1));
}

__device__ __forceinline__ void cp_async16(void* smem_dst, const void* gmem_src) {
    unsigned s = (unsigned)__cvta_generic_to_shared(smem_dst);
    asm volatile("cp.async.ca.shared.global [%0], [%1], 16;\n"
                 :: "r"(s), "l"(gmem_src));
}

// swizzled uint2 index within a 128x8 plane: 16B-block xor keeps cp.async
// 16B-aligned and makes all fragment LDS.64 patterns conflict-free.
__device__ __forceinline__ int swz(int row, int kp) {
    return row * 8 + ((((kp >> 1) ^ (row & 3)) << 1) | (kp & 1));
}

// ---------------------------------------------------------------------------
// W split+transpose precompute: g_wt[mat][n][kp] = (bf16x2 hi, bf16x2 lo)
// of (W[2kp][n], W[2kp+1][n])
// ---------------------------------------------------------------------------
__global__ __launch_bounds__(256) void w_split_t(
    const float* __restrict__ Wq, const float* __restrict__ Wk,
    const float* __restrict__ Wv)
{
    const int i = blockIdx.x * 256 + threadIdx.x;
    if (i >= 3 * CDIM * 64) return;
    const int mat = i / (CDIM * 64);
    const int rem = i - mat * CDIM * 64;
    const int n   = rem >> 6;
    const int kp  = rem & 63;
    const float* __restrict__ W = (mat == 0) ? Wq : (mat == 1) ? Wk : Wv;
    const float w0 = W[(2 * kp    ) * CDIM + n];
    const float w1 = W[(2 * kp + 1) * CDIM + n];
    g_wt[i] = splitpack_bf16(w0, w1);
}

// ---------------------------------------------------------------------------
// Combined mid kernel:
//   blocks [0, GEMM_BLOCKS)          : bf16 3-term QKV GEMM tiles
//   blocks [GEMM_BLOCKS, +PE_BLOCKS) : positional precompute (a3)
// ---------------------------------------------------------------------------
__global__ __launch_bounds__(256, 2) void mid_fused(
    const float* __restrict__ x,
    const float* __restrict__ bq, const float* __restrict__ bk,
    const float* __restrict__ bv,
    const float* __restrict__ p,  const int* __restrict__ idx,
    const float* __restrict__ Wp1, const float* __restrict__ bp1,
    const float* __restrict__ gp,  const float* __restrict__ betap)
{
    const int bid = blockIdx.x;
    const int tid = threadIdx.x;

    if (bid >= GEMM_BLOCKS) {
        // ---------------- positional precompute ----------------
        const int t = (bid - GEMM_BLOCKS) * 256 + tid;
        if (t >= NPTS * SDIM) return;
        const int n = t >> 4;
        const int j = idx[t];

        const float pr0 = p[j * 3 + 0] - p[n * 3 + 0];
        const float pr1 = p[j * 3 + 1] - p[n * 3 + 1];
        const float pr2 = p[j * 3 + 2] - p[n * 3 + 2];

        float t0 = fmaf(pr2, Wp1[6], fmaf(pr1, Wp1[3], fmaf(pr0, Wp1[0], bp1[0])));
        float t1 = fmaf(pr2, Wp1[7], fmaf(pr1, Wp1[4], fmaf(pr0, Wp1[1], bp1[1])));
        float t2 = fmaf(pr2, Wp1[8], fmaf(pr1, Wp1[5], fmaf(pr0, Wp1[2], bp1[2])));
        const float mp  = (t0 + t1 + t2) * (1.f / 3.f);
        const float e0 = t0 - mp, e1 = t1 - mp, e2 = t2 - mp;
        const float vp  = (e0 * e0 + e1 * e1 + e2 * e2) * (1.f / 3.f);
        const float ivp = rsqrtf(vp + EPSLN);
        const float a0 = fmaxf(fmaf(e0 * ivp, gp[0], betap[0]), 0.f);
        const float a1 = fmaxf(fmaf(e1 * ivp, gp[1], betap[1]), 0.f);
        const float a2 = fmaxf(fmaf(e2 * ivp, gp[2], betap[2]), 0.f);
        g_a3[t] = make_float4(a0, a1, a2, 0.f);
        return;
    }

    // ---------------- bf16 3-term GEMM tile, K-chunk = 16 ----------------
    extern __shared__ uint2 smu[];
    uint2* sx = smu;            // [2][128 rows][8 kp] swizzled (hi,lo)
    uint2* sw = smu + SX_U2;    // [2][128 n   ][8 kp] swizzled (hi,lo)

    const int mat   = bid % 3;
    const int mtile = bid / 3;
    const int row0  = mtile * 128;

    const float* __restrict__ bias = (mat == 0) ? bq : (mat == 1) ? bk : bv;
    float* __restrict__ out        = (mat == 0) ? g_q : (mat == 1) ? g_k : g_v;
    const uint2* __restrict__ Wt   = g_wt + (size_t)mat * CDIM * 64;

    const int lane   = tid & 31;
    const int wid    = tid >> 5;
    const int warp_m = wid & 3;
    const int warp_n = wid >> 2;
    const int lg  = lane >> 2;
    const int lt  = lane & 3;

    const int xrow  = tid >> 1;               // 0..127
    const int xkp0  = (tid & 1) * 4;          // first of 4 uint2 (kp)
    const bool xvalid = (row0 + xrow) < NPTS;
    const float* xbase = x + (size_t)(row0 + xrow) * CDIM + (tid & 1) * 8;

    float d[2][8][4];
#pragma unroll
    for (int g = 0; g < 2; g++)
#pragma unroll
        for (int nb = 0; nb < 8; nb++)
#pragma unroll
            for (int c = 0; c < 4; c++) d[g][nb][c] = 0.f;

    auto stage_w = [&](int st, int c) {       // c = chunk index, kp0 = c*8
#pragma unroll
        for (int i = 0; i < 2; i++) {
            const int li = tid * 2 + i;       // 0..511
            const int n  = li >> 2;           // 0..127
            const int bq16 = li & 3;          // 16B block (2 uint2)
            const int dst = st * 1024 + n * 8 + ((bq16 ^ (n & 3)) << 1);
            cp_async16(&sw[dst], Wt + (size_t)n * 64 + c * 8 + bq16 * 2);
        }
        asm volatile("cp.async.commit_group;");
    };
    auto store_x = [&](int st, float4 xa, float4 xb) {
        const int base = st * 1024;
        sx[base + swz(xrow, xkp0 + 0)] = splitpack_bf16(xa.x, xa.y);
        sx[base + swz(xrow, xkp0 + 1)] = splitpack_bf16(xa.z, xa.w);
        sx[base + swz(xrow, xkp0 + 2)] = splitpack_bf16(xb.x, xb.y);
        sx[base + swz(xrow, xkp0 + 3)] = splitpack_bf16(xb.z, xb.w);
    };

    // prologue: chunk 0
    stage_w(0, 0);
    {
        float4 xa = make_float4(0.f, 0.f, 0.f, 0.f), xb = xa;
        if (xvalid) { xa = *(const float4*)(xbase); xb = *(const float4*)(xbase + 4); }
        store_x(0, xa, xb);
    }
    asm volatile("cp.async.wait_group 0;");
    __syncthreads();

#pragma unroll 1
    for (int c = 0; c < 8; c++) {
        const int cur = c & 1;
        const bool more = (c < 7);

        float4 xa, xb;
        if (more) {
            stage_w(cur ^ 1, c + 1);
            xa = make_float4(0.f, 0.f, 0.f, 0.f); xb = xa;
            if (xvalid) {
                xa = *(const float4*)(xbase + (c + 1) * 16);
                xb = *(const float4*)(xbase + (c + 1) * 16 + 4);
            }
        }

        // ---- compute on stage cur (one k16 chunk) ----
        const int cb = cur * 1024;
        unsigned ah[2][4], al[2][4];
#pragma unroll
        for (int g = 0; g < 2; g++) {
            const int rb = warp_m * 32 + g * 16;
            const uint2 v0 = sx[cb + swz(rb + lg,     lt    )];
            const uint2 v1 = sx[cb + swz(rb + lg + 8, lt    )];
            const uint2 v2 = sx[cb + swz(rb + lg,     lt + 4)];
            const uint2 v3 = sx[cb + swz(rb + lg + 8, lt + 4)];
            ah[g][0] = v0.x; al[g][0] = v0.y;
            ah[g][1] = v1.x; al[g][1] = v1.y;
            ah[g][2] = v2.x; al[g][2] = v2.y;
            ah[g][3] = v3.x; al[g][3] = v3.y;
        }
#pragma unroll
        for (int nb = 0; nb < 8; nb++) {
            const int ncol = warp_n * 64 + nb * 8 + lg;
            const uint2 b0 = sw[cb + swz(ncol, lt    )];
            const uint2 b1 = sw[cb + swz(ncol, lt + 4)];
#pragma unroll
            for (int g = 0; g < 2; g++) {
                mma_bf16(d[g][nb], ah[g], b0.x, b1.x);   // hi * hi
                mma_bf16(d[g][nb], ah[g], b0.y, b1.y);   // hi * lo
                mma_bf16(d[g][nb], al[g], b0.x, b1.x);   // lo * hi
            }
        }

        if (more) {
            store_x(cur ^ 1, xa, xb);
            asm volatile("cp.async.wait_group 0;");
        }
        __syncthreads();
    }

    // ---- epilogue: add bias, write ----
#pragma unroll
    for (int nb = 0; nb < 8; nb++) {
        const int col = warp_n * 64 + nb * 8 + lt * 2;
        const float2 bs = *(const float2*)(bias + col);
#pragma unroll
        for (int g = 0; g < 2; g++) {
            const int rbase = row0 + warp_m * 32 + g * 16 + lg;
            if (rbase < NPTS) {
                float2 o = make_float2(d[g][nb][0] + bs.x, d[g][nb][1] + bs.y);
                *(float2*)(out + (size_t)rbase * CDIM + col) = o;
            }
            if (rbase + 8 < NPTS) {
                float2 o = make_float2(d[g][nb][2] + bs.x, d[g][nb][3] + bs.y);
                *(float2*)(out + (size_t)(rbase + 8) * CDIM + col) = o;
            }
        }
    }
}

// ---------------------------------------------------------------------------
// Fused point-transformer kernel — R11 version verbatim (best known).
// ---------------------------------------------------------------------------
__global__ __launch_bounds__(256, 3) void pt_fused(
    const int*   __restrict__ idx,
    const float* __restrict__ Wp2, const float* __restrict__ bp2,
    const float* __restrict__ gw1, const float* __restrict__ betaw1,
    const float* __restrict__ Ww1, const float* __restrict__ bw1,
    const float* __restrict__ gw2, const float* __restrict__ betaw2,
    const float* __restrict__ Ww2, const float* __restrict__ bw2,
    float* __restrict__ out)
{
    __shared__ float sWw1[16][16];
    __shared__ float sWw2[16][16];
    __shared__ int   sidx[8][SDIM];
    __shared__ float slog[8][SDIM][HDIM];
    __shared__ float sa[8][4][HDIM][16];

    const int tid  = threadIdx.x;
    const int pt   = tid >> 5;
    const int lane = tid & 31;
    const int n    = blockIdx.x * 8 + pt;
    const int ch4  = lane * 4;
    const int qq   = lane & 3;
    const int d4   = qq * 4;
    const int hh   = lane >> 2;
    const unsigned FULL = 0xffffffffu;

    {
        float* w1f = &sWw1[0][0];
        float* w2f = &sWw2[0][0];
        w1f[tid] = Ww1[tid];
        w2f[tid] = Ww2[tid];
    }
    if (lane < SDIM) sidx[pt][lane] = idx[n * SDIM + lane];
    __syncthreads();

    const float4 xq4   = *(const float4*)(g_q + (size_t)n * CDIM + ch4);
    const float4 wp2c0 = *(const float4*)(Wp2 + 0 * CDIM + ch4);
    const float4 wp2c1 = *(const float4*)(Wp2 + 1 * CDIM + ch4);
    const float4 wp2c2 = *(const float4*)(Wp2 + 2 * CDIM + ch4);
    const float4 bp24  = *(const float4*)(bp2 + ch4);
    const float4 g14   = *(const float4*)(gw1    + d4);
    const float4 be14  = *(const float4*)(betaw1 + d4);
    const float4 b14   = *(const float4*)(bw1    + d4);
    const float4 g24   = *(const float4*)(gw2    + d4);
    const float4 be24  = *(const float4*)(betaw2 + d4);

    float4 cm;
    {
        float s0 = 0.f, s1 = 0.f, s2 = 0.f, s3 = 0.f;
#pragma unroll
        for (int j = 0; j < 4; j++) {
            const float4 v0 = *(const float4*)&sWw2[d4 + 0][j * 4];
            const float4 v1 = *(const float4*)&sWw2[d4 + 1][j * 4];
            const float4 v2 = *(const float4*)&sWw2[d4 + 2][j * 4];
            const float4 v3 = *(const float4*)&sWw2[d4 + 3][j * 4];
            s0 += v0.x + v0.y + v0.z + v0.w;
            s1 += v1.x + v1.y + v1.z + v1.w;
            s2 += v2.x + v2.y + v2.z + v2.w;
            s3 += v3.x + v3.y + v3.z + v3.w;
        }
        cm = make_float4(s0 * (1.f / 16.f), s1 * (1.f / 16.f),
                         s2 * (1.f / 16.f), s3 * (1.f / 16.f));
    }
    float mbw2;
    {
        const float4 b2 = *(const float4*)(bw2 + d4);
        float sb = b2.x + b2.y + b2.z + b2.w;
        sb += __shfl_xor_sync(FULL, sb, 1, 4);
        sb += __shfl_xor_sync(FULL, sb, 2, 4);
        mbw2 = sb * (1.f / 16.f);
    }

    const int sslot = ((qq + hh) & 3) * 4;

#pragma unroll 1
    for (int s = 0; s < SDIM; s += 4) {
        float4 r[4], a3[4];
#pragma unroll
        for (int u = 0; u < 4; u++) {
            const int j = sidx[pt][s + u];
            r[u]  = *(const float4*)(g_k + (size_t)j * CDIM + ch4);
            a3[u] = g_a3[n * SDIM + s + u];
        }

        float sm[4], sq[4];
#pragma unroll
        for (int u = 0; u < 4; u++) {
            r[u].x += fmaf(a3[u].x, wp2c0.x, fmaf(a3[u].y, wp2c1.x, fmaf(a3[u].z, wp2c2.x, bp24.x))) - xq4.x;
            r[u].y += fmaf(a3[u].x, wp2c0.y, fmaf(a3[u].y, wp2c1.y, fmaf(a3[u].z, wp2c2.y, bp24.y))) - xq4.y;
            r[u].z += fmaf(a3[u].x, wp2c0.z, fmaf(a3[u].y, wp2c1.z, fmaf(a3[u].z, wp2c2.z, bp24.z))) - xq4.z;
            r[u].w += fmaf(a3[u].x, wp2c0.w, fmaf(a3[u].y, wp2c1.w, fmaf(a3[u].z, wp2c2.w, bp24.w))) - xq4.w;
            sm[u] = r[u].x + r[u].y + r[u].z + r[u].w;
            sq[u] = r[u].x * r[u].x + r[u].y * r[u].y + r[u].z * r[u].z + r[u].w * r[u].w;
        }
#pragma unroll
        for (int u = 0; u < 4; u++) { sm[u] += __shfl_xor_sync(FULL, sm[u], 1, 4);
                                      sq[u] += __shfl_xor_sync(FULL, sq[u], 1, 4); }
#pragma unroll
        for (int u = 0; u < 4; u++) { sm[u] += __shfl_xor_sync(FULL, sm[u], 2, 4);
                                      sq[u] += __shfl_xor_sync(FULL, sq[u], 2, 4); }
#pragma unroll
        for (int u = 0; u < 4; u++) {
            const float mean = sm[u] * (1.f / 16.f);
            const float var  = fmaf(-mean, mean, sq[u] * (1.f / 16.f));
            const float inv  = rsqrtf(var + EPSLN);
            float4 a;
            a.x = fmaxf(fmaf((r[u].x - mean) * inv, g14.x, be14.x), 0.f);
            a.y = fmaxf(fmaf((r[u].y - mean) * inv, g14.y, be14.y), 0.f);
            a.z = fmaxf(fmaf((r[u].z - mean) * inv, g14.z, be14.z), 0.f);
            a.w = fmaxf(fmaf((r[u].w - mean) * inv, g14.w, be14.w), 0.f);
            *(float4*)&sa[pt][u][hh][sslot] = a;
        }
        __syncwarp();

        float4 w[4];
#pragma unroll
        for (int u = 0; u < 4; u++) w[u] = b14;
#pragma unroll
        for (int q = 0; q < 4; q++) {
            const float4 c0 = *(const float4*)&sWw1[q * 4 + 0][d4];
            const float4 c1 = *(const float4*)&sWw1[q * 4 + 1][d4];
            const float4 c2 = *(const float4*)&sWw1[q * 4 + 2][d4];
            const float4 c3 = *(const float4*)&sWw1[q * 4 + 3][d4];
            const int ps = ((q + hh) & 3) * 4;
#pragma unroll
            for (int u = 0; u < 4; u++) {
                const float4 a = *(const float4*)&sa[pt][u][hh][ps];
                w[u].x = fmaf(a.x, c0.x, fmaf(a.y, c1.x, fmaf(a.z, c2.x, fmaf(a.w, c3.x, w[u].x))));
                w[u].y = fmaf(a.x, c0.y, fmaf(a.y, c1.y, fmaf(a.z, c2.y, fmaf(a.w, c3.y, w[u].y))));
                w[u].z = fmaf(a.x, c0.z, fmaf(a.y, c1.z, fmaf(a.z, c2.z, fmaf(a.w, c3.z, w[u].z))));
                w[u].w = fmaf(a.x, c0.w, fmaf(a.y, c1.w, fmaf(a.z, c2.w, fmaf(a.w, c3.w, w[u].w))));
            }
        }
        __syncwarp();

#pragma unroll
        for (int u = 0; u < 4; u++) {
            sm[u] = w[u].x + w[u].y + w[u].z + w[u].w;
            sq[u] = w[u].x * w[u].x + w[u].y * w[u].y + w[u].z * w[u].z + w[u].w * w[u].w;
        }
#pragma unroll
        for (int u = 0; u < 4; u++) { sm[u] += __shfl_xor_sync(FULL, sm[u], 1, 4);
                                      sq[u] += __shfl_xor_sync(FULL, sq[u], 1, 4); }
#pragma unroll
        for (int u = 0; u < 4; u++) { sm[u] += __shfl_xor_sync(FULL, sm[u], 2, 4);
                                      sq[u] += __shfl_xor_sync(FULL, sq[u], 2, 4); }

        float l[4];
#pragma unroll
        for (int u = 0; u < 4; u++) {
            const float mean = sm[u] * (1.f / 16.f);
            const float var  = fmaf(-mean, mean, sq[u] * (1.f / 16.f));
            const float inv  = rsqrtf(var + EPSLN);
            const float ex = fmaxf(fmaf((w[u].x - mean) * inv, g24.x, be24.x), 0.f);
            const float ey = fmaxf(fmaf((w[u].y - mean) * inv, g24.y, be24.y), 0.f);
            const float ez = fmaxf(fmaf((w[u].z - mean) * inv, g24.z, be24.z), 0.f);
            const float ew = fmaxf(fmaf((w[u].w - mean) * inv, g24.w, be24.w), 0.f);
            l[u] = fmaf(ex, cm.x, fmaf(ey, cm.y, fmaf(ez, cm.z, ew * cm.w)));
        }
#pragma unroll
        for (int u = 0; u < 4; u++) l[u] += __shfl_xor_sync(FULL, l[u], 1, 4);
#pragma unroll
        for (int u = 0; u < 4; u++) l[u] += __shfl_xor_sync(FULL, l[u], 2, 4);
        if (qq == 0) {
#pragma unroll
            for (int u = 0; u < 4; u++) slog[pt][s + u][hh] = l[u] + mbw2;
        }
    }
    __syncwarp();

    float mx = -1e30f;
#pragma unroll
    for (int s = 0; s < SDIM; s++) mx = fmaxf(mx, slog[pt][s][hh]);
    float se = 0.f;
    float ev[SDIM];
#pragma unroll
    for (int s = 0; s < SDIM; s++) {
        ev[s] = __expf(slog[pt][s][hh] - mx);
        se += ev[s];
    }
    const float rse = 1.f / se;

    float4 acc = make_float4(0.f, 0.f, 0.f, 0.f);
    float A0 = 0.f, A1 = 0.f, A2 = 0.f;
#pragma unroll 2
    for (int s = 0; s < SDIM; s++) {
        const float wg = ev[s] * rse;
        const int j = sidx[pt][s];
        const float4 vg = *(const float4*)(g_v + (size_t)j * CDIM + ch4);
        const float4 a3 = g_a3[n * SDIM + s];
        acc.x = fmaf(vg.x, wg, acc.x);
        acc.y = fmaf(vg.y, wg, acc.y);
        acc.z = fmaf(vg.z, wg, acc.z);
        acc.w = fmaf(vg.w, wg, acc.w);
        A0 = fmaf(a3.x, wg, A0);
        A1 = fmaf(a3.y, wg, A1);
        A2 = fmaf(a3.z, wg, A2);
    }
    float4 o;
    o.x = acc.x + fmaf(A0, wp2c0.x, fmaf(A1, wp2c1.x, fmaf(A2, wp2c2.x, bp24.x)));
    o.y = acc.y + fmaf(A0, wp2c0.y, fmaf(A1, wp2c1.y, fmaf(A2, wp2c2.y, bp24.y)));
    o.z = acc.z + fmaf(A0, wp2c0.z, fmaf(A1, wp2c1.z, fmaf(A2, wp2c2.z, bp24.z)));
    o.w = acc.w + fmaf(A0, wp2c0.w, fmaf(A1, wp2c1.w, fmaf(A2, wp2c2.w, bp24.w)));
    *(float4*)(out + (size_t)n * CDIM + ch4) = o;
}

// ---------------------------------------------------------------------------
extern "C" void kernel_launch(void* const* d_in, const int* in_sizes, int n_in,
                              void* d_out, int out_size)
{
    const float* p      = (const float*)d_in[0];
    const float* x      = (const float*)d_in[1];
    const int*   idx    = (const int*)  d_in[2];
    const float* Wq     = (const float*)d_in[3];
    const float* bq     = (const float*)d_in[4];
    const float* Wk     = (const float*)d_in[5];
    const float* bk     = (const float*)d_in[6];
    const float* Wv     = (const float*)d_in[7];
    const float* bv     = (const float*)d_in[8];
    const float* Wp1    = (const float*)d_in[9];
    const float* bp1    = (const float*)d_in[10];
    const float* gp     = (const float*)d_in[11];
    const float* betap  = (const float*)d_in[12];
    const float* Wp2    = (const float*)d_in[13];
    const float* bp2    = (const float*)d_in[14];
    const float* gw1    = (const float*)d_in[15];
    const float* betaw1 = (const float*)d_in[16];
    const float* Ww1    = (const float*)d_in[17];
    const float* bw1    = (const float*)d_in[18];
    const float* gw2    = (const float*)d_in[19];
    const float* betaw2 = (const float*)d_in[20];
    const float* Ww2    = (const float*)d_in[21];
    const float* bw2    = (const float*)d_in[22];
    float* out = (float*)d_out;

    cudaFuncSetAttribute(mid_fused, cudaFuncAttributeMaxDynamicSharedMemorySize,
                         SMEM_BYTES);

    w_split_t<<<(3 * CDIM * 64 + 255) / 256, 256>>>(Wq, Wk, Wv);

    mid_fused<<<GEMM_BLOCKS + PE_BLOCKS, 256, SMEM_BYTES>>>(
        x, bq, bk, bv, p, idx, Wp1, bp1, gp, betap);

    pt_fused<<<NPTS / 8, 256>>>(idx,
                                Wp2, bp2,
                                gw1, betaw1, Ww1, bw1,
                                gw2, betaw2, Ww2, bw2, out);
}

// round 14
// speedup vs baseline: 1.0872x; 1.0291x over previous
#include <cuda_runtime.h>
#include <cuda_bf16.h>
#include <math.h>

// Problem constants
#define NPTS   30000
#define CDIM   128
#define SDIM   16      // neighbors
#define HDIM   8       // heads
#define DDIM   16      // dims per head
#define OSDIM  16      // O / SHARE
#define EPSLN  1e-5f

#define MTILES 235                 // ceil(30000/128)
#define GEMM_BLOCKS (MTILES * 3)
#define PE_BLOCKS   ((NPTS * SDIM + 255) / 256)

// dynamic smem (uint2 units): sx = 2 stages x 128 rows x 8 kp, sw same
#define SX_U2 (2 * 128 * 8)
#define SW_U2 (2 * 128 * 8)
#define SMEM_BYTES ((SX_U2 + SW_U2) * 8)

// Scratch (no cudaMalloc allowed)
__device__ float  g_q[NPTS * CDIM];
__device__ float  g_k[NPTS * CDIM];
__device__ float  g_v[NPTS * CDIM];
__device__ float4 g_a3[NPTS * SDIM];     // relu(ln(pr@Wp1+bp1)) per (n,s)
__device__ uint2  g_wt[3 * CDIM * 64];   // W transposed: [mat][n][kp] -> (hi bf16x2, lo bf16x2)

// ---------------------------------------------------------------------------
// f32x2 packed-math helpers (Blackwell; ptxas never auto-emits FFMA2)
// ---------------------------------------------------------------------------
#define PK2(d, lo, hi) \
    asm("mov.b64 %0, {%1, %2};" : "=l"(d) : "f"(lo), "f"(hi))
#define UPK2(lo, hi, s) \
    asm("mov.b64 {%0, %1}, %2;" : "=f"(lo), "=f"(hi) : "l"(s))
#define FMA2(d, a, b, c) \
    asm("fma.rn.f32x2 %0, %1, %2, %3;" : "=l"(d) : "l"(a), "l"(b), "l"(c))
#define ADD2(d, a, b) \
    asm("add.rn.f32x2 %0, %1, %2;" : "=l"(d) : "l"(a), "l"(b))
typedef unsigned long long ull;

// ---------------------------------------------------------------------------
// bf16 split helpers
// ---------------------------------------------------------------------------
__device__ __forceinline__ uint2 splitpack_bf16(float a, float b) {
    const __nv_bfloat16 ha = __float2bfloat16(a);
    const __nv_bfloat16 hb = __float2bfloat16(b);
    const float ra = a - __bfloat162float(ha);
    const float rb = b - __bfloat162float(hb);
    uint2 o;
    o.x = (unsigned)__bfloat16_as_ushort(ha) |
          ((unsigned)__bfloat16_as_ushort(hb) << 16);
    o.y = (unsigned)__bfloat16_as_ushort(__float2bfloat16(ra)) |
          ((unsigned)__bfloat16_as_ushort(__float2bfloat16(rb)) << 16);
    return o;
}

__device__ __forceinline__ void mma_bf16(float* d, const unsigned* a,
                                         unsigned b0, unsigned b1) {
    asm volatile(
        "mma.sync.aligned.m16n8k16.row.col.f32.bf16.bf16.f32 "
        "{%0,%1,%2,%3}, {%4,%5,%6,%7}, {%8,%9}, {%0,%1,%2,%3};"
        : "+f"(d[0]), "+f"(d[1]), "+f"(d[2]), "+f"(d[3])
        : "r"(a[0]), "r"(a[1]), "r"(a[2]), "r"(a[3]), "r"(b0), "r"(b1));
}

__device__ __forceinline__ void cp_async16(void* smem_dst, const void* gmem_src) {
    unsigned s = (unsigned)__cvta_generic_to_shared(smem_dst);
    asm volatile("cp.async.ca.shared.global [%0], [%1], 16;\n"
                 :: "r"(s), "l"(gmem_src));
}

// swizzled uint2 index within a 128x8 plane
__device__ __forceinline__ int swz(int row, int kp) {
    return row * 8 + ((((kp >> 1) ^ (row & 3)) << 1) | (kp & 1));
}

// ---------------------------------------------------------------------------
// W split+transpose precompute (unchanged from R13)
// ---------------------------------------------------------------------------
__global__ __launch_bounds__(256) void w_split_t(
    const float* __restrict__ Wq, const float* __restrict__ Wk,
    const float* __restrict__ Wv)
{
    const int i = blockIdx.x * 256 + threadIdx.x;
    if (i >= 3 * CDIM * 64) return;
    const int mat = i / (CDIM * 64);
    const int rem = i - mat * (CDIM * 64);
    const int n   = rem >> 6;
    const int kp  = rem & 63;
    const float* __restrict__ W = (mat == 0) ? Wq : (mat == 1) ? Wk : Wv;
    const float w0 = W[(2 * kp    ) * CDIM + n];
    const float w1 = W[(2 * kp + 1) * CDIM + n];
    g_wt[i] = splitpack_bf16(w0, w1);
}

// ---------------------------------------------------------------------------
// Combined mid kernel (unchanged from R13)
// ---------------------------------------------------------------------------
__global__ __launch_bounds__(256, 2) void mid_fused(
    const float* __restrict__ x,
    const float* __restrict__ bq, const float* __restrict__ bk,
    const float* __restrict__ bv,
    const float* __restrict__ p,  const int* __restrict__ idx,
    const float* __restrict__ Wp1, const float* __restrict__ bp1,
    const float* __restrict__ gp,  const float* __restrict__ betap)
{
    const int bid = blockIdx.x;
    const int tid = threadIdx.x;

    if (bid >= GEMM_BLOCKS) {
        const int t = (bid - GEMM_BLOCKS) * 256 + tid;
        if (t >= NPTS * SDIM) return;
        const int n = t >> 4;
        const int j = idx[t];

        const float pr0 = p[j * 3 + 0] - p[n * 3 + 0];
        const float pr1 = p[j * 3 + 1] - p[n * 3 + 1];
        const float pr2 = p[j * 3 + 2] - p[n * 3 + 2];

        float t0 = fmaf(pr2, Wp1[6], fmaf(pr1, Wp1[3], fmaf(pr0, Wp1[0], bp1[0])));
        float t1 = fmaf(pr2, Wp1[7], fmaf(pr1, Wp1[4], fmaf(pr0, Wp1[1], bp1[1])));
        float t2 = fmaf(pr2, Wp1[8], fmaf(pr1, Wp1[5], fmaf(pr0, Wp1[2], bp1[2])));
        const float mp  = (t0 + t1 + t2) * (1.f / 3.f);
        const float e0 = t0 - mp, e1 = t1 - mp, e2 = t2 - mp;
        const float vp  = (e0 * e0 + e1 * e1 + e2 * e2) * (1.f / 3.f);
        const float ivp = rsqrtf(vp + EPSLN);
        const float a0 = fmaxf(fmaf(e0 * ivp, gp[0], betap[0]), 0.f);
        const float a1 = fmaxf(fmaf(e1 * ivp, gp[1], betap[1]), 0.f);
        const float a2 = fmaxf(fmaf(e2 * ivp, gp[2], betap[2]), 0.f);
        g_a3[t] = make_float4(a0, a1, a2, 0.f);
        return;
    }

    extern __shared__ uint2 smu[];
    uint2* sx = smu;
    uint2* sw = smu + SX_U2;

    const int mat   = bid % 3;
    const int mtile = bid / 3;
    const int row0  = mtile * 128;

    const float* __restrict__ bias = (mat == 0) ? bq : (mat == 1) ? bk : bv;
    float* __restrict__ out        = (mat == 0) ? g_q : (mat == 1) ? g_k : g_v;
    const uint2* __restrict__ Wt   = g_wt + (size_t)mat * CDIM * 64;

    const int lane   = tid & 31;
    const int wid    = tid >> 5;
    const int warp_m = wid & 3;
    const int warp_n = wid >> 2;
    const int lg  = lane >> 2;
    const int lt  = lane & 3;

    const int xrow  = tid >> 1;
    const int xkp0  = (tid & 1) * 4;
    const bool xvalid = (row0 + xrow) < NPTS;
    const float* xbase = x + (size_t)(row0 + xrow) * CDIM + (tid & 1) * 8;

    float d[2][8][4];
#pragma unroll
    for (int g = 0; g < 2; g++)
#pragma unroll
        for (int nb = 0; nb < 8; nb++)
#pragma unroll
            for (int c = 0; c < 4; c++) d[g][nb][c] = 0.f;

    auto stage_w = [&](int st, int c) {
#pragma unroll
        for (int i = 0; i < 2; i++) {
            const int li = tid * 2 + i;
            const int n  = li >> 2;
            const int bq16 = li & 3;
            const int dst = st * 1024 + n * 8 + ((bq16 ^ (n & 3)) << 1);
            cp_async16(&sw[dst], Wt + (size_t)n * 64 + c * 8 + bq16 * 2);
        }
        asm volatile("cp.async.commit_group;");
    };
    auto store_x = [&](int st, float4 xa, float4 xb) {
        const int base = st * 1024;
        sx[base + swz(xrow, xkp0 + 0)] = splitpack_bf16(xa.x, xa.y);
        sx[base + swz(xrow, xkp0 + 1)] = splitpack_bf16(xa.z, xa.w);
        sx[base + swz(xrow, xkp0 + 2)] = splitpack_bf16(xb.x, xb.y);
        sx[base + swz(xrow, xkp0 + 3)] = splitpack_bf16(xb.z, xb.w);
    };

    stage_w(0, 0);
    {
        float4 xa = make_float4(0.f, 0.f, 0.f, 0.f), xb = xa;
        if (xvalid) { xa = *(const float4*)(xbase); xb = *(const float4*)(xbase + 4); }
        store_x(0, xa, xb);
    }
    asm volatile("cp.async.wait_group 0;");
    __syncthreads();

#pragma unroll 1
    for (int c = 0; c < 8; c++) {
        const int cur = c & 1;
        const bool more = (c < 7);

        float4 xa, xb;
        if (more) {
            stage_w(cur ^ 1, c + 1);
            xa = make_float4(0.f, 0.f, 0.f, 0.f); xb = xa;
            if (xvalid) {
                xa = *(const float4*)(xbase + (c + 1) * 16);
                xb = *(const float4*)(xbase + (c + 1) * 16 + 4);
            }
        }

        const int cb = cur * 1024;
        unsigned ah[2][4], al[2][4];
#pragma unroll
        for (int g = 0; g < 2; g++) {
            const int rb = warp_m * 32 + g * 16;
            const uint2 v0 = sx[cb + swz(rb + lg,     lt    )];
            const uint2 v1 = sx[cb + swz(rb + lg + 8, lt    )];
            const uint2 v2 = sx[cb + swz(rb + lg,     lt + 4)];
            const uint2 v3 = sx[cb + swz(rb + lg + 8, lt + 4)];
            ah[g][0] = v0.x; al[g][0] = v0.y;
            ah[g][1] = v1.x; al[g][1] = v1.y;
            ah[g][2] = v2.x; al[g][2] = v2.y;
            ah[g][3] = v3.x; al[g][3] = v3.y;
        }
#pragma unroll
        for (int nb = 0; nb < 8; nb++) {
            const int ncol = warp_n * 64 + nb * 8 + lg;
            const uint2 b0 = sw[cb + swz(ncol, lt    )];
            const uint2 b1 = sw[cb + swz(ncol, lt + 4)];
#pragma unroll
            for (int g = 0; g < 2; g++) {
                mma_bf16(d[g][nb], ah[g], b0.x, b1.x);
                mma_bf16(d[g][nb], ah[g], b0.y, b1.y);
                mma_bf16(d[g][nb], al[g], b0.x, b1.x);
            }
        }

        if (more) {
            store_x(cur ^ 1, xa, xb);
            asm volatile("cp.async.wait_group 0;");
        }
        __syncthreads();
    }

#pragma unroll
    for (int nb = 0; nb < 8; nb++) {
        const int col = warp_n * 64 + nb * 8 + lt * 2;
        const float2 bs = *(const float2*)(bias + col);
#pragma unroll
        for (int g = 0; g < 2; g++) {
            const int rbase = row0 + warp_m * 32 + g * 16 + lg;
            if (rbase < NPTS) {
                float2 o = make_float2(d[g][nb][0] + bs.x, d[g][nb][1] + bs.y);
                *(float2*)(out + (size_t)rbase * CDIM + col) = o;
            }
            if (rbase + 8 < NPTS) {
                float2 o = make_float2(d[g][nb][2] + bs.x, d[g][nb][3] + bs.y);
                *(float2*)(out + (size_t)(rbase + 8) * CDIM + col) = o;
            }
        }
    }
}

// ---------------------------------------------------------------------------
// Fused point-transformer kernel — R11 structure with f32x2-packed pe/r and
// matvec1 (FFMA2 path; ptxas never emits it from plain C++).
// ---------------------------------------------------------------------------
__global__ __launch_bounds__(256, 3) void pt_fused(
    const int*   __restrict__ idx,
    const float* __restrict__ Wp2, const float* __restrict__ bp2,
    const float* __restrict__ gw1, const float* __restrict__ betaw1,
    const float* __restrict__ Ww1, const float* __restrict__ bw1,
    const float* __restrict__ gw2, const float* __restrict__ betaw2,
    const float* __restrict__ Ww2, const float* __restrict__ bw2,
    float* __restrict__ out)
{
    __shared__ float sWw1[16][16];
    __shared__ float sWw2[16][16];
    __shared__ int   sidx[8][SDIM];
    __shared__ float slog[8][SDIM][HDIM];
    __shared__ float sa[8][4][HDIM][16];

    const int tid  = threadIdx.x;
    const int pt   = tid >> 5;
    const int lane = tid & 31;
    const int n    = blockIdx.x * 8 + pt;
    const int ch4  = lane * 4;
    const int qq   = lane & 3;
    const int d4   = qq * 4;
    const int hh   = lane >> 2;
    const unsigned FULL = 0xffffffffu;

    {
        float* w1f = &sWw1[0][0];
        float* w2f = &sWw2[0][0];
        w1f[tid] = Ww1[tid];
        w2f[tid] = Ww2[tid];
    }
    if (lane < SDIM) sidx[pt][lane] = idx[n * SDIM + lane];
    __syncthreads();

    const float4 xq4   = *(const float4*)(g_q + (size_t)n * CDIM + ch4);
    const float4 wp2c0 = *(const float4*)(Wp2 + 0 * CDIM + ch4);
    const float4 wp2c1 = *(const float4*)(Wp2 + 1 * CDIM + ch4);
    const float4 wp2c2 = *(const float4*)(Wp2 + 2 * CDIM + ch4);
    const float4 bp24  = *(const float4*)(bp2 + ch4);
    const float4 g14   = *(const float4*)(gw1    + d4);
    const float4 be14  = *(const float4*)(betaw1 + d4);
    const float4 b14   = *(const float4*)(bw1    + d4);
    const float4 g24   = *(const float4*)(gw2    + d4);
    const float4 be24  = *(const float4*)(betaw2 + d4);

    float4 cm;
    {
        float s0 = 0.f, s1 = 0.f, s2 = 0.f, s3 = 0.f;
#pragma unroll
        for (int j = 0; j < 4; j++) {
            const float4 v0 = *(const float4*)&sWw2[d4 + 0][j * 4];
            const float4 v1 = *(const float4*)&sWw2[d4 + 1][j * 4];
            const float4 v2 = *(const float4*)&sWw2[d4 + 2][j * 4];
            const float4 v3 = *(const float4*)&sWw2[d4 + 3][j * 4];
            s0 += v0.x + v0.y + v0.z + v0.w;
            s1 += v1.x + v1.y + v1.z + v1.w;
            s2 += v2.x + v2.y + v2.z + v2.w;
            s3 += v3.x + v3.y + v3.z + v3.w;
        }
        cm = make_float4(s0 * (1.f / 16.f), s1 * (1.f / 16.f),
                         s2 * (1.f / 16.f), s3 * (1.f / 16.f));
    }
    float mbw2;
    {
        const float4 b2 = *(const float4*)(bw2 + d4);
        float sb = b2.x + b2.y + b2.z + b2.w;
        sb += __shfl_xor_sync(FULL, sb, 1, 4);
        sb += __shfl_xor_sync(FULL, sb, 2, 4);
        mbw2 = sb * (1.f / 16.f);
    }

    // hoisted f32x2 constants
    ull wp2c0_01, wp2c0_23, wp2c1_01, wp2c1_23, wp2c2_01, wp2c2_23;
    PK2(wp2c0_01, wp2c0.x, wp2c0.y); PK2(wp2c0_23, wp2c0.z, wp2c0.w);
    PK2(wp2c1_01, wp2c1.x, wp2c1.y); PK2(wp2c1_23, wp2c1.z, wp2c1.w);
    PK2(wp2c2_01, wp2c2.x, wp2c2.y); PK2(wp2c2_23, wp2c2.z, wp2c2.w);
    // pe base folded with -xq: r = kg + (a3@Wp2 + (bp2 - xq))
    ull peb01, peb23;
    {
        const float e0 = bp24.x - xq4.x, e1 = bp24.y - xq4.y;
        const float e2 = bp24.z - xq4.z, e3 = bp24.w - xq4.w;
        PK2(peb01, e0, e1); PK2(peb23, e2, e3);
    }
    ull b14_01, b14_23;
    PK2(b14_01, b14.x, b14.y); PK2(b14_23, b14.z, b14.w);

    const int sslot = ((qq + hh) & 3) * 4;

#pragma unroll 1
    for (int s = 0; s < SDIM; s += 4) {
        float4 kg[4], a3[4];
#pragma unroll
        for (int u = 0; u < 4; u++) {
            const int j = sidx[pt][s + u];
            kg[u] = *(const float4*)(g_k + (size_t)j * CDIM + ch4);
            a3[u] = g_a3[n * SDIM + s + u];
        }

        // r = kg + pe + (bp2 - xq)  via packed FMA; LN1 sums
        float4 r[4];
        float sm[4], sq[4];
#pragma unroll
        for (int u = 0; u < 4; u++) {
            ull a0p, a1p, a2p;
            PK2(a0p, a3[u].x, a3[u].x);
            PK2(a1p, a3[u].y, a3[u].y);
            PK2(a2p, a3[u].z, a3[u].z);
            ull t01, t23;
            FMA2(t01, a0p, wp2c0_01, peb01);
            FMA2(t23, a0p, wp2c0_23, peb23);
            FMA2(t01, a1p, wp2c1_01, t01);
            FMA2(t23, a1p, wp2c1_23, t23);
            FMA2(t01, a2p, wp2c2_01, t01);
            FMA2(t23, a2p, wp2c2_23, t23);
            ull kg01, kg23;
            PK2(kg01, kg[u].x, kg[u].y);
            PK2(kg23, kg[u].z, kg[u].w);
            ull r01, r23;
            ADD2(r01, kg01, t01);
            ADD2(r23, kg23, t23);
            UPK2(r[u].x, r[u].y, r01);
            UPK2(r[u].z, r[u].w, r23);
            sm[u] = r[u].x + r[u].y + r[u].z + r[u].w;
            sq[u] = r[u].x * r[u].x + r[u].y * r[u].y + r[u].z * r[u].z + r[u].w * r[u].w;
        }
#pragma unroll
        for (int u = 0; u < 4; u++) { sm[u] += __shfl_xor_sync(FULL, sm[u], 1, 4);
                                      sq[u] += __shfl_xor_sync(FULL, sq[u], 1, 4); }
#pragma unroll
        for (int u = 0; u < 4; u++) { sm[u] += __shfl_xor_sync(FULL, sm[u], 2, 4);
                                      sq[u] += __shfl_xor_sync(FULL, sq[u], 2, 4); }
#pragma unroll
        for (int u = 0; u < 4; u++) {
            const float mean = sm[u] * (1.f / 16.f);
            const float var  = fmaf(-mean, mean, sq[u] * (1.f / 16.f));
            const float inv  = rsqrtf(var + EPSLN);
            float4 a;
            a.x = fmaxf(fmaf((r[u].x - mean) * inv, g14.x, be14.x), 0.f);
            a.y = fmaxf(fmaf((r[u].y - mean) * inv, g14.y, be14.y), 0.f);
            a.z = fmaxf(fmaf((r[u].z - mean) * inv, g14.z, be14.z), 0.f);
            a.w = fmaxf(fmaf((r[u].w - mean) * inv, g14.w, be14.w), 0.f);
            *(float4*)&sa[pt][u][hh][sslot] = a;
        }
        __syncwarp();

        // matvec1 via packed FFMA2: weights shared across all 4 tokens
        ull w01[4], w23[4];
#pragma unroll
        for (int u = 0; u < 4; u++) { w01[u] = b14_01; w23[u] = b14_23; }
#pragma unroll
        for (int q = 0; q < 4; q++) {
            const float4 c0 = *(const float4*)&sWw1[q * 4 + 0][d4];
            const float4 c1 = *(const float4*)&sWw1[q * 4 + 1][d4];
            const float4 c2 = *(const float4*)&sWw1[q * 4 + 2][d4];
            const float4 c3 = *(const float4*)&sWw1[q * 4 + 3][d4];
            ull c0_01, c0_23, c1_01, c1_23, c2_01, c2_23, c3_01, c3_23;
            PK2(c0_01, c0.x, c0.y); PK2(c0_23, c0.z, c0.w);
            PK2(c1_01, c1.x, c1.y); PK2(c1_23, c1.z, c1.w);
            PK2(c2_01, c2.x, c2.y); PK2(c2_23, c2.z, c2.w);
            PK2(c3_01, c3.x, c3.y); PK2(c3_23, c3.z, c3.w);
            const int ps = ((q + hh) & 3) * 4;
#pragma unroll
            for (int u = 0; u < 4; u++) {
                const float4 a = *(const float4*)&sa[pt][u][hh][ps];
                ull ax, ay, az, aw;
                PK2(ax, a.x, a.x); PK2(ay, a.y, a.y);
                PK2(az, a.z, a.z); PK2(aw, a.w, a.w);
                FMA2(w01[u], ax, c0_01, w01[u]);
                FMA2(w23[u], ax, c0_23, w23[u]);
                FMA2(w01[u], ay, c1_01, w01[u]);
                FMA2(w23[u], ay, c1_23, w23[u]);
                FMA2(w01[u], az, c2_01, w01[u]);
                FMA2(w23[u], az, c2_23, w23[u]);
                FMA2(w01[u], aw, c3_01, w01[u]);
                FMA2(w23[u], aw, c3_23, w23[u]);
            }
        }
        __syncwarp();

        // unpack, LN2 sums (single-pass, batched shuffles)
        float4 w[4];
#pragma unroll
        for (int u = 0; u < 4; u++) {
            UPK2(w[u].x, w[u].y, w01[u]);
            UPK2(w[u].z, w[u].w, w23[u]);
            sm[u] = w[u].x + w[u].y + w[u].z + w[u].w;
            sq[u] = w[u].x * w[u].x + w[u].y * w[u].y + w[u].z * w[u].z + w[u].w * w[u].w;
        }
#pragma unroll
        for (int u = 0; u < 4; u++) { sm[u] += __shfl_xor_sync(FULL, sm[u], 1, 4);
                                      sq[u] += __shfl_xor_sync(FULL, sq[u], 1, 4); }
#pragma unroll
        for (int u = 0; u < 4; u++) { sm[u] += __shfl_xor_sync(FULL, sm[u], 2, 4);
                                      sq[u] += __shfl_xor_sync(FULL, sq[u], 2, 4); }

        float l[4];
#pragma unroll
        for (int u = 0; u < 4; u++) {
            const float mean = sm[u] * (1.f / 16.f);
            const float var  = fmaf(-mean, mean, sq[u] * (1.f / 16.f));
            const float inv  = rsqrtf(var + EPSLN);
            const float ex = fmaxf(fmaf((w[u].x - mean) * inv, g24.x, be24.x), 0.f);
            const float ey = fmaxf(fmaf((w[u].y - mean) * inv, g24.y, be24.y), 0.f);
            const float ez = fmaxf(fmaf((w[u].z - mean) * inv, g24.z, be24.z), 0.f);
            const float ew = fmaxf(fmaf((w[u].w - mean) * inv, g24.w, be24.w), 0.f);
            l[u] = fmaf(ex, cm.x, fmaf(ey, cm.y, fmaf(ez, cm.z, ew * cm.w)));
        }
#pragma unroll
        for (int u = 0; u < 4; u++) l[u] += __shfl_xor_sync(FULL, l[u], 1, 4);
#pragma unroll
        for (int u = 0; u < 4; u++) l[u] += __shfl_xor_sync(FULL, l[u], 2, 4);
        if (qq == 0) {
#pragma unroll
            for (int u = 0; u < 4; u++) slog[pt][s + u][hh] = l[u] + mbw2;
        }
    }
    __syncwarp();

    float mx = -1e30f;
#pragma unroll
    for (int s = 0; s < SDIM; s++) mx = fmaxf(mx, slog[pt][s][hh]);
    float se = 0.f;
    float ev[SDIM];
#pragma unroll
    for (int s = 0; s < SDIM; s++) {
        ev[s] = __expf(slog[pt][s][hh] - mx);
        se += ev[s];
    }
    const float rse = 1.f / se;

    float4 acc = make_float4(0.f, 0.f, 0.f, 0.f);
    float A0 = 0.f, A1 = 0.f, A2 = 0.f;
#pragma unroll 2
    for (int s = 0; s < SDIM; s++) {
        const float wg = ev[s] * rse;
        const int j = sidx[pt][s];
        const float4 vg = *(const float4*)(g_v + (size_t)j * CDIM + ch4);
        const float4 a3 = g_a3[n * SDIM + s];
        acc.x = fmaf(vg.x, wg, acc.x);
        acc.y = fmaf(vg.y, wg, acc.y);
        acc.z = fmaf(vg.z, wg, acc.z);
        acc.w = fmaf(vg.w, wg, acc.w);
        A0 = fmaf(a3.x, wg, A0);
        A1 = fmaf(a3.y, wg, A1);
        A2 = fmaf(a3.z, wg, A2);
    }
    float4 o;
    o.x = acc.x + fmaf(A0, wp2c0.x, fmaf(A1, wp2c1.x, fmaf(A2, wp2c2.x, bp24.x)));
    o.y = acc.y + fmaf(A0, wp2c0.y, fmaf(A1, wp2c1.y, fmaf(A2, wp2c2.y, bp24.y)));
    o.z = acc.z + fmaf(A0, wp2c0.z, fmaf(A1, wp2c1.z, fmaf(A2, wp2c2.z, bp24.z)));
    o.w = acc.w + fmaf(A0, wp2c0.w, fmaf(A1, wp2c1.w, fmaf(A2, wp2c2.w, bp24.w)));
    *(float4*)(out + (size_t)n * CDIM + ch4) = o;
}

// ---------------------------------------------------------------------------
extern "C" void kernel_launch(void* const* d_in, const int* in_sizes, int n_in,
                              void* d_out, int out_size)
{
    const float* p      = (const float*)d_in[0];
    const float* x      = (const float*)d_in[1];
    const int*   idx    = (const int*)  d_in[2];
    const float* Wq     = (const float*)d_in[3];
    const float* bq     = (const float*)d_in[4];
    const float* Wk     = (const float*)d_in[5];
    const float* bk     = (const float*)d_in[6];
    const float* Wv     = (const float*)d_in[7];
    const float* bv     = (const float*)d_in[8];
    const float* Wp1    = (const float*)d_in[9];
    const float* bp1    = (const float*)d_in[10];
    const float* gp     = (const float*)d_in[11];
    const float* betap  = (const float*)d_in[12];
    const float* Wp2    = (const float*)d_in[13];
    const float* bp2    = (const float*)d_in[14];
    const float* gw1    = (const float*)d_in[15];
    const float* betaw1 = (const float*)d_in[16];
    const float* Ww1    = (const float*)d_in[17];
    const float* bw1    = (const float*)d_in[18];
    const float* gw2    = (const float*)d_in[19];
    const float* betaw2 = (const float*)d_in[20];
    const float* Ww2    = (const float*)d_in[21];
    const float* bw2    = (const float*)d_in[22];
    float* out = (float*)d_out;

    cudaFuncSetAttribute(mid_fused, cudaFuncAttributeMaxDynamicSharedMemorySize,
                         SMEM_BYTES);

    w_split_t<<<(3 * CDIM * 64 + 255) / 256, 256>>>(Wq, Wk, Wv);

    mid_fused<<<GEMM_BLOCKS + PE_BLOCKS, 256, SMEM_BYTES>>>(
        x, bq, bk, bv, p, idx, Wp1, bp1, gp, betap);

    pt_fused<<<NPTS / 8, 256>>>(idx,
                                Wp2, bp2,
                                gw1, betaw1, Ww1, bw1,
                                gw2, betaw2, Ww2, bw2, out);
}